// round 9
// baseline (speedup 1.0000x reference)
#include <cuda_runtime.h>
#include <math.h>

#define BB     128
#define DD     128
#define NMEM   100000
#define KTOT   8194     // 2 pos + 8192 neg
#define K2     8193     // idx[:,1:]
#define NEGK   8192
#define TAUF   0.07f
#define KDT    3.0f
#define MSH    20.0f    // fixed logsumexp shift (logits bounded by ~18)
#define CHUNKS 8
#define KCH    1025     // ceil(8194/8)

// -------- device scratch (static: no runtime allocation) --------
__device__ float g_c01[BB * KTOT];   // mem0 . emb1 / tau   (inter, student/teacher)
__device__ float g_c10[BB * KTOT];   // mem1 . emb0 / tau
__device__ float g_l0 [BB * K2];     // mem0 . emb0 / tau   (intra, idx[:,1:])
__device__ float g_l1 [BB * K2];     // mem1 . emb1 / tau
__device__ float g_stat[BB][12];     // per-b: s1X,sTX,uX, s1Y,sTY,uY, s1Z,sTZ,uZ, s1W,sTW,uW

__device__ __forceinline__ float wredsum(float v) {
    v += __shfl_xor_sync(0xffffffffu, v, 16);
    v += __shfl_xor_sync(0xffffffffu, v, 8);
    v += __shfl_xor_sync(0xffffffffu, v, 4);
    v += __shfl_xor_sync(0xffffffffu, v, 2);
    v += __shfl_xor_sync(0xffffffffu, v, 1);
    return v;
}

// ================= Kernel A: gather + 4 dots per (b,k) =================
// grid (CHUNKS, BB), 256 threads. One warp per k-iteration.
// Lane l holds float4 slice [4l..4l+3] of emb0[b], emb1[b]; loads matching
// float4 of mem0/mem1 row idx[b,k] (coalesced 512B per row per warp).
// 9-shuffle folded reduction lands: lane0=dot01, lane1=dot10, lane2=dot00, lane3=dot11.
__global__ void __launch_bounds__(256, 4) k_gather(
    const float4* __restrict__ emb0, const float4* __restrict__ emb1,
    const float4* __restrict__ mem0, const float4* __restrict__ mem1,
    const int* __restrict__ pos_idx, const int* __restrict__ neg_idx)
{
    const int b    = blockIdx.y;
    const int c    = blockIdx.x;
    const int w    = threadIdx.x >> 5;
    const int lane = threadIdx.x & 31;

    const float4 e0 = emb0[b * 32 + lane];
    const float4 e1 = emb1[b * 32 + lane];

    const int kbeg = c * KCH;
    const int kend = (kbeg + KCH < KTOT) ? (kbeg + KCH) : KTOT;
    const float invtau = 1.0f / TAUF;

    #pragma unroll 2
    for (int k = kbeg + w; k < kend; k += 8) {
        const int n = (k < 2) ? pos_idx[b * 2 + k] : neg_idx[b * NEGK + (k - 2)];
        const float4 m0 = mem0[n * 32 + lane];
        const float4 m1 = mem1[n * 32 + lane];

        float p01 = m0.x*e1.x + m0.y*e1.y + m0.z*e1.z + m0.w*e1.w;
        float p10 = m1.x*e0.x + m1.y*e0.y + m1.z*e0.z + m1.w*e0.w;
        float p00 = m0.x*e0.x + m0.y*e0.y + m0.z*e0.z + m0.w*e0.w;
        float p11 = m1.x*e1.x + m1.y*e1.y + m1.z*e1.z + m1.w*e1.w;

        // fold 1 (xor 1): A <- {even: p01, odd: p10}, Bv <- {even: p00, odd: p11}
        float t0 = __shfl_xor_sync(0xffffffffu, p01, 1);
        float t1 = __shfl_xor_sync(0xffffffffu, p10, 1);
        float A  = (lane & 1) ? (p10 + t1) : (p01 + t0);
        float t2 = __shfl_xor_sync(0xffffffffu, p00, 1);
        float t3 = __shfl_xor_sync(0xffffffffu, p11, 1);
        float Bv = (lane & 1) ? (p11 + t3) : (p00 + t2);
        // fold 2 (xor 2): C <- {bit1==0: A, bit1==1: Bv}
        float tA = __shfl_xor_sync(0xffffffffu, A, 2);
        float tB = __shfl_xor_sync(0xffffffffu, Bv, 2);
        float C  = (lane & 2) ? (Bv + tB) : (A + tA);
        // standard butterfly over remaining bits
        C += __shfl_xor_sync(0xffffffffu, C, 4);
        C += __shfl_xor_sync(0xffffffffu, C, 8);
        C += __shfl_xor_sync(0xffffffffu, C, 16);

        const float v = C * invtau;
        if      (lane == 0) g_c01[b * KTOT + k] = v;
        else if (lane == 1) g_c10[b * KTOT + k] = v;
        else if (lane == 2) { if (k >= 1) g_l0[b * K2 + (k - 1)] = v; }
        else if (lane == 3) { if (k >= 1) g_l1[b * K2 + (k - 1)] = v; }
    }
}

// ================= Kernel B: per-b softmax/KL statistics =================
// One CTA per b. Fully coalesced reads of the 4 logit rows; fixed shift MSH.
__global__ void __launch_bounds__(256) k_stats()
{
    const int b   = blockIdx.x;
    const int tid = threadIdx.x;
    const float i3 = 1.0f / KDT;

    const float* __restrict__ X = g_c01 + b * KTOT;
    const float* __restrict__ Y = g_c10 + b * KTOT;
    const float* __restrict__ Z = g_l0  + b * K2;
    const float* __restrict__ W = g_l1  + b * K2;

    float a0=0.f,a1=0.f,a2=0.f,a3=0.f,a4=0.f,a5=0.f;
    float a6=0.f,a7=0.f,a8=0.f,a9=0.f,a10=0.f,a11=0.f;

    for (int k = tid; k < KTOT; k += 256) {
        float x = X[k], y = Y[k];
        float xs = x - MSH, ys = y - MSH;
        a0 += __expf(xs);
        float etx = __expf(xs * i3);
        a1 += etx; a2 += etx * (x - y);
        a3 += __expf(ys);
        float ety = __expf(ys * i3);
        a4 += ety; a5 += ety * (y - x);
        if (k < K2) {
            float z = Z[k], ww = W[k];
            float zs = z - MSH, ws = ww - MSH;
            a6 += __expf(zs);
            float etz = __expf(zs * i3);
            a7 += etz; a8 += etz * (z - ww);
            a9 += __expf(ws);
            float etw = __expf(ws * i3);
            a10 += etw; a11 += etw * (ww - z);
        }
    }

    float acc[12] = {a0,a1,a2,a3,a4,a5,a6,a7,a8,a9,a10,a11};
    __shared__ float sm[8][12];
    const int w = tid >> 5, lane = tid & 31;
    #pragma unroll
    for (int i = 0; i < 12; i++) {
        float r = wredsum(acc[i]);
        if (lane == 0) sm[w][i] = r;
    }
    __syncthreads();
    if (tid < 12) {
        float s = 0.f;
        #pragma unroll
        for (int j = 0; j < 8; j++) s += sm[j][tid];
        g_stat[b][tid] = s;
    }
}

// ================= Kernel D: combine per-b stats -> 4 scalars =================
// soft terms: summing both KL directions cancels the log-partition terms:
//   kl(X|Y)+kl(Y|X) per b = (uX/sTX + uY/sTY)/T ; x T^2 / B overall.
__global__ void k_final(float* __restrict__ out)
{
    const int b = threadIdx.x;   // 128 threads
    float s1X=g_stat[b][0], sTX=g_stat[b][1], uX=g_stat[b][2];
    float s1Y=g_stat[b][3], sTY=g_stat[b][4], uY=g_stat[b][5];
    float s1Z=g_stat[b][6], sTZ=g_stat[b][7], uZ=g_stat[b][8];
    float s1W=g_stat[b][9], sTW=g_stat[b][10],uW=g_stat[b][11];

    float X0 = g_c01[b * KTOT + 0], X1 = g_c01[b * KTOT + 1];
    float Y0 = g_c10[b * KTOT + 0], Y1 = g_c10[b * KTOT + 1];
    float Z0 = g_l0 [b * K2 + 0],   W0 = g_l1 [b * K2 + 0];

    float lse1X = MSH + logf(s1X), lse1Y = MSH + logf(s1Y);
    float lse1Z = MSH + logf(s1Z), lse1W = MSH + logf(s1W);

    float icl  = lse1X + lse1Y - 0.5f * (X0 + X1 + Y0 + Y1);
    float sicl = KDT * (uX / sTX + uY / sTY);
    float vcl  = (lse1Z - Z0) + (lse1W - W0);
    float svcl = KDT * (uZ / sTZ + uW / sTW);

    vcl = wredsum(vcl); svcl = wredsum(svcl);
    icl = wredsum(icl); sicl = wredsum(sicl);

    __shared__ float sm[4][4];
    const int w = b >> 5, lane = b & 31;
    if (lane == 0) { sm[w][0] = vcl; sm[w][1] = svcl; sm[w][2] = icl; sm[w][3] = sicl; }
    __syncthreads();
    if (b == 0) {
        float r0=0.f, r1=0.f, r2=0.f, r3=0.f;
        #pragma unroll
        for (int j = 0; j < 4; j++) { r0+=sm[j][0]; r1+=sm[j][1]; r2+=sm[j][2]; r3+=sm[j][3]; }
        const float ib = 1.0f / (float)BB;
        out[0] = r0 * ib;   // vcl
        out[1] = r1 * ib;   // soft_vcl
        out[2] = r2 * ib;   // icl
        out[3] = r3 * ib;   // soft_icl
    }
}

// ================= Kernel C: copy mems to output =================
__global__ void __launch_bounds__(256) k_copy(
    const float4* __restrict__ m0, const float4* __restrict__ m1,
    float4* __restrict__ o)
{
    const int total = NMEM * 32;  // float4 per mem
    for (long i = (long)blockIdx.x * 256 + threadIdx.x; i < 2L * total;
         i += (long)gridDim.x * 256) {
        float4 v = (i < total) ? m0[i] : m1[i - total];
        o[i] = v;
    }
}

// ================= Kernel E: momentum row updates (one warp per (net,b)) ======
__global__ void k_update(
    const float* __restrict__ emb0, const float* __restrict__ emb1,
    const float4* __restrict__ mem0, const float4* __restrict__ mem1,
    const int* __restrict__ pos, float4* __restrict__ o)
{
    const int gw   = (blockIdx.x * blockDim.x + threadIdx.x) >> 5;
    const int lane = threadIdx.x & 31;
    if (gw >= 2 * BB) return;
    const int net = gw >> 7, b = gw & (BB - 1);
    const int p = pos[b * 2];

    // duplicate-index handling: last occurrence wins (deterministic)
    bool dup = false;
    for (int j = lane; j < BB; j += 32)
        if (j > b && pos[j * 2] == p) dup = true;
    if (__ballot_sync(0xffffffffu, dup)) return;

    const float4* mem = net ? mem1 : mem0;
    const float*  emb = net ? emb1 : emb0;
    float4 m = mem[p * 32 + lane];
    float4 e = reinterpret_cast<const float4*>(emb)[b * 32 + lane];
    float4 u;
    u.x = 0.5f * m.x + 0.5f * e.x;
    u.y = 0.5f * m.y + 0.5f * e.y;
    u.z = 0.5f * m.z + 0.5f * e.z;
    u.w = 0.5f * m.w + 0.5f * e.w;
    float s = u.x*u.x + u.y*u.y + u.z*u.z + u.w*u.w;
    s = wredsum(s);
    float inv = rsqrtf(s);
    u.x *= inv; u.y *= inv; u.z *= inv; u.w *= inv;
    o[(long)net * (NMEM * 32) + p * 32 + lane] = u;
}

// ================= launch =================
extern "C" void kernel_launch(void* const* d_in, const int* in_sizes, int n_in,
                              void* d_out, int out_size)
{
    const float* emb0 = (const float*)d_in[0];
    const float* emb1 = (const float*)d_in[1];
    const float* mem0 = (const float*)d_in[2];
    const float* mem1 = (const float*)d_in[3];
    const int* pos_idx = (const int*)d_in[4];
    const int* neg_idx = (const int*)d_in[5];
    float* out = (float*)d_out;

    (void)in_sizes; (void)n_in; (void)out_size;

    dim3 gA(CHUNKS, BB);
    k_gather<<<gA, 256>>>(
        (const float4*)emb0, (const float4*)emb1,
        (const float4*)mem0, (const float4*)mem1,
        pos_idx, neg_idx);

    k_stats<<<BB, 256>>>();

    // new_mem0 / new_mem1 live at out+4 (16B-aligned since d_out is 256B-aligned)
    float4* omem = (float4*)(out + 4);
    k_copy<<<2048, 256>>>((const float4*)mem0, (const float4*)mem1, omem);
    k_update<<<32, 256>>>(emb0, emb1,
                          (const float4*)mem0, (const float4*)mem1,
                          pos_idx, omem);

    k_final<<<1, 128>>>(out);
}